// round 1
// baseline (speedup 1.0000x reference)
#include <cuda_runtime.h>
#include <math.h>
#include <float.h>

// ---------------------------------------------------------------------------
// AngularLoss: loss = logsumexp_i( 4*t2*dot(a_i+p_i, n_i) - 2*(1+t2)*dot(a_i,p_i) )
// N = 262144 rows, D = 128. Pure HBM-streaming reduction (384 MiB -> 1 float).
//
// Pass 1: one warp per row (float4 per lane), warp-shuffle dot reduce,
//         online logsumexp per warp, block-combined (m,s) partial per block.
// Pass 2: single block folds all block partials -> M + log(S).
// Deterministic (fixed reduction order, no atomics), graph-capturable,
// allocation-free (__device__ scratch).
// ---------------------------------------------------------------------------

#define P1_BLOCKS 2048
#define P1_THREADS 256
#define WARPS_PER_BLOCK (P1_THREADS / 32)

__device__ float2 g_partials[P1_BLOCKS];

__device__ __forceinline__ void lse_combine(float& m, float& s, float om, float os) {
    float nm = fmaxf(m, om);
    s = s * __expf(m - nm) + os * __expf(om - nm);
    m = nm;
}

__global__ void __launch_bounds__(P1_THREADS)
angular_pass1(const float* __restrict__ A,
              const float* __restrict__ P,
              const float* __restrict__ Ng,
              const int*   __restrict__ alpha_raw,
              int N)
{
    // alpha scalar: int32 expected; tolerate fp32 bit pattern just in case.
    int raw = alpha_raw[0];
    float alpha = (raw > 1000000 || raw < -1000000) ? __int_as_float(raw) : (float)raw;
    float ang = alpha * (3.14159265358979323846f / 180.0f);
    float t  = tanf(ang);
    float t2 = t * t;
    float c1 = 4.0f * t2;
    float c2 = -2.0f * (1.0f + t2);

    const float4* A4 = (const float4*)A;
    const float4* P4 = (const float4*)P;
    const float4* N4 = (const float4*)Ng;

    int lane = threadIdx.x & 31;
    int warp = threadIdx.x >> 5;
    int gwarp  = blockIdx.x * WARPS_PER_BLOCK + warp;
    int nwarps = gridDim.x * WARPS_PER_BLOCK;

    float m = -FLT_MAX;
    float s = 0.0f;

    for (int row = gwarp; row < N; row += nwarps) {
        size_t base = (size_t)row * 32 + lane;   // float4 index (D=128 -> 32 float4/row)
        float4 a = A4[base];
        float4 p = P4[base];
        float4 n = N4[base];

        float ap  = a.x * p.x + a.y * p.y + a.z * p.z + a.w * p.w;
        float apn = (a.x + p.x) * n.x + (a.y + p.y) * n.y
                  + (a.z + p.z) * n.z + (a.w + p.w) * n.w;

        #pragma unroll
        for (int o = 16; o > 0; o >>= 1) {
            ap  += __shfl_xor_sync(0xFFFFFFFFu, ap,  o);
            apn += __shfl_xor_sync(0xFFFFFFFFu, apn, o);
        }
        float f = c1 * apn + c2 * ap;   // identical across lanes

        float nm = fmaxf(m, f);
        s = s * __expf(m - nm) + __expf(f - nm);
        m = nm;
    }

    // Block reduce: lane 0 of each warp publishes its (m,s); thread 0 folds them.
    __shared__ float sm[WARPS_PER_BLOCK];
    __shared__ float ss[WARPS_PER_BLOCK];
    if (lane == 0) { sm[warp] = m; ss[warp] = s; }
    __syncthreads();
    if (threadIdx.x == 0) {
        float M = -FLT_MAX, S = 0.0f;
        #pragma unroll
        for (int w = 0; w < WARPS_PER_BLOCK; w++)
            lse_combine(M, S, sm[w], ss[w]);
        g_partials[blockIdx.x] = make_float2(M, S);
    }
}

__global__ void __launch_bounds__(256)
angular_pass2(float* __restrict__ out, int nblocks)
{
    int tid = threadIdx.x;
    float m = -FLT_MAX, s = 0.0f;

    for (int i = tid; i < nblocks; i += 256) {
        float2 pp = g_partials[i];
        lse_combine(m, s, pp.x, pp.y);
    }

    // warp reduce (combine (m,s) pairs)
    #pragma unroll
    for (int o = 16; o > 0; o >>= 1) {
        float om = __shfl_xor_sync(0xFFFFFFFFu, m, o);
        float os = __shfl_xor_sync(0xFFFFFFFFu, s, o);
        lse_combine(m, s, om, os);
    }

    __shared__ float sm[8];
    __shared__ float ss[8];
    int warp = tid >> 5, lane = tid & 31;
    if (lane == 0) { sm[warp] = m; ss[warp] = s; }
    __syncthreads();
    if (tid == 0) {
        float M = -FLT_MAX, S = 0.0f;
        #pragma unroll
        for (int w = 0; w < 8; w++)
            lse_combine(M, S, sm[w], ss[w]);
        out[0] = M + logf(S);
    }
}

extern "C" void kernel_launch(void* const* d_in, const int* in_sizes, int n_in,
                              void* d_out, int out_size)
{
    const float* A  = (const float*)d_in[0];
    const float* P  = (const float*)d_in[1];
    const float* Ng = (const float*)d_in[2];
    const int*   al = (const int*)d_in[3];
    float* out = (float*)d_out;

    int N = in_sizes[0] / 128;   // D = 128

    angular_pass1<<<P1_BLOCKS, P1_THREADS>>>(A, P, Ng, al, N);
    angular_pass2<<<1, 256>>>(out, P1_BLOCKS);
}

// round 2
// speedup vs baseline: 1.0105x; 1.0105x over previous
#include <cuda_runtime.h>
#include <math.h>
#include <float.h>

// ---------------------------------------------------------------------------
// AngularLoss: loss = logsumexp_i( 4*t2*dot(a_i+p_i, n_i) - 2*(1+t2)*dot(a_i,p_i) )
// N = 262144 rows, D = 128. Pure HBM-streaming reduction (384 MiB -> 1 float).
//
// Single fused kernel:
//   - one warp per row chunk (float4/lane), warp-shuffle dot reduce
//   - online logsumexp per warp, block partial (m,s) -> __device__ scratch
//   - last-block-done (atomic ticket + threadfence) folds all partials in
//     FIXED index order -> deterministic; counter self-resets for graph replay.
// Single wave: grid = 148 SMs x 8 blocks = 1184 persistent blocks.
// ---------------------------------------------------------------------------

#define P1_BLOCKS 1184
#define P1_THREADS 256
#define WARPS_PER_BLOCK (P1_THREADS / 32)

__device__ float2 g_partials[P1_BLOCKS];
__device__ unsigned int g_ticket;   // zero-initialized; self-resets each call

__device__ __forceinline__ void lse_combine(float& m, float& s, float om, float os) {
    float nm = fmaxf(m, om);
    s = s * __expf(m - nm) + os * __expf(om - nm);
    m = nm;
}

__global__ void __launch_bounds__(P1_THREADS)
angular_fused(const float* __restrict__ A,
              const float* __restrict__ P,
              const float* __restrict__ Ng,
              const int*   __restrict__ alpha_raw,
              float* __restrict__ out,
              int N)
{
    // alpha scalar: int32 expected; tolerate fp32 bit pattern just in case.
    int raw = alpha_raw[0];
    float alpha = (raw > 1000000 || raw < -1000000) ? __int_as_float(raw) : (float)raw;
    float ang = alpha * (3.14159265358979323846f / 180.0f);
    float t  = tanf(ang);
    float t2 = t * t;
    float c1 = 4.0f * t2;
    float c2 = -2.0f * (1.0f + t2);

    const float4* A4 = (const float4*)A;
    const float4* P4 = (const float4*)P;
    const float4* N4 = (const float4*)Ng;

    int lane = threadIdx.x & 31;
    int warp = threadIdx.x >> 5;
    int gwarp  = blockIdx.x * WARPS_PER_BLOCK + warp;
    int nwarps = P1_BLOCKS * WARPS_PER_BLOCK;

    float m = -FLT_MAX;
    float s = 0.0f;

    for (int row = gwarp; row < N; row += nwarps) {
        size_t base = (size_t)row * 32 + lane;   // float4 index (D=128 -> 32 float4/row)
        float4 a = A4[base];
        float4 p = P4[base];
        float4 n = N4[base];

        float ap  = a.x * p.x + a.y * p.y + a.z * p.z + a.w * p.w;
        float apn = (a.x + p.x) * n.x + (a.y + p.y) * n.y
                  + (a.z + p.z) * n.z + (a.w + p.w) * n.w;

        #pragma unroll
        for (int o = 16; o > 0; o >>= 1) {
            ap  += __shfl_xor_sync(0xFFFFFFFFu, ap,  o);
            apn += __shfl_xor_sync(0xFFFFFFFFu, apn, o);
        }
        float f = c1 * apn + c2 * ap;   // identical across lanes

        // branchless online LSE update (common path: one exp)
        if (f <= m) {
            s += __expf(f - m);
        } else {
            s = s * __expf(m - f) + 1.0f;
            m = f;
        }
    }

    // Block reduce: lane 0 of each warp publishes (m,s); thread 0 folds them.
    __shared__ float sm[WARPS_PER_BLOCK];
    __shared__ float ss[WARPS_PER_BLOCK];
    __shared__ bool s_last;
    if (lane == 0) { sm[warp] = m; ss[warp] = s; }
    __syncthreads();

    if (threadIdx.x == 0) {
        float M = -FLT_MAX, S = 0.0f;
        #pragma unroll
        for (int w = 0; w < WARPS_PER_BLOCK; w++)
            lse_combine(M, S, sm[w], ss[w]);
        g_partials[blockIdx.x] = make_float2(M, S);
        __threadfence();
        unsigned int t_old = atomicAdd(&g_ticket, 1u);
        s_last = (t_old == (unsigned int)(P1_BLOCKS - 1));
    }
    __syncthreads();

    if (!s_last) return;

    // Last block: fold all block partials (fixed index order -> deterministic).
    {
        int tid = threadIdx.x;
        float fm = -FLT_MAX, fs = 0.0f;
        for (int i = tid; i < P1_BLOCKS; i += P1_THREADS) {
            float2 pp = g_partials[i];
            lse_combine(fm, fs, pp.x, pp.y);
        }
        #pragma unroll
        for (int o = 16; o > 0; o >>= 1) {
            float om = __shfl_xor_sync(0xFFFFFFFFu, fm, o);
            float os = __shfl_xor_sync(0xFFFFFFFFu, fs, o);
            lse_combine(fm, fs, om, os);
        }
        __shared__ float fsm[WARPS_PER_BLOCK];
        __shared__ float fss[WARPS_PER_BLOCK];
        if (lane == 0) { fsm[warp] = fm; fss[warp] = fs; }
        __syncthreads();
        if (threadIdx.x == 0) {
            float M = -FLT_MAX, S = 0.0f;
            #pragma unroll
            for (int w = 0; w < WARPS_PER_BLOCK; w++)
                lse_combine(M, S, fsm[w], fss[w]);
            out[0] = M + logf(S);
            g_ticket = 0;   // reset for next graph replay
        }
    }
}

extern "C" void kernel_launch(void* const* d_in, const int* in_sizes, int n_in,
                              void* d_out, int out_size)
{
    const float* A  = (const float*)d_in[0];
    const float* P  = (const float*)d_in[1];
    const float* Ng = (const float*)d_in[2];
    const int*   al = (const int*)d_in[3];
    float* out = (float*)d_out;

    int N = in_sizes[0] / 128;   // D = 128

    angular_fused<<<P1_BLOCKS, P1_THREADS>>>(A, P, Ng, al, out, N);
}